// round 14
// baseline (speedup 1.0000x reference)
#include <cuda_runtime.h>
#include <cuda_bf16.h>
#include <math_constants.h>

#define FEAT 50
#define NPOS 2500
#define NBOX 22500
#define CIN 2048
#define CMID 1024
#define KJ (CIN*9)
#define NOUT 45
#define NSPLIT 16
#define PRE 6000
#define POST 300
#define NW 188
#define MASKW 192
#define NBIN 65536

#define WT_TILE 1728           // ull per 4-channel group: 9 planes x 12 (cc,ky) x 16 og
#define WT_KX   192            // plane stride = 12*16
#define E_TILE  432            // 4 ch x 4 rows x 27 cols

#define SUMW_BLOCKS 3240       // (CIN*9*NOUT)/256
#define BIAS_BLOCKS 45
#define ZERO_BLOCKS 256
#define PREP_BLOCKS (SUMW_BLOCKS + BIAS_BLOCKS + ZERO_BLOCKS)

#define NBLK 148               // persistent post-kernel blocks (co-resident)

typedef unsigned long long ull;

__device__ __forceinline__ ull pack2(float lo, float hi) {
    ull d; asm("mov.b64 %0, {%1, %2};" : "=l"(d) : "f"(lo), "f"(hi)); return d;
}
__device__ __forceinline__ void unpack2(ull p, float& lo, float& hi) {
    asm("mov.b64 {%0, %1}, %2;" : "=f"(lo), "=f"(hi) : "l"(p));
}
__device__ __forceinline__ ull ffma2(ull a, ull b, ull c) {
    ull d; asm("fma.rn.f32x2 %0, %1, %2, %3;" : "=l"(d) : "l"(a), "l"(b), "l"(c)); return d;
}

// ------------------ scratch ------------------
__device__ float      g_WfP0[(size_t)KJ * NOUT];
__device__ float      g_WfP1[(size_t)KJ * NOUT];
__device__ ull        g_WeffT[(size_t)(CIN / 4) * WT_TILE];
__device__ float      g_bias[NOUT];
__device__ float      g_Psplit[NSPLIT * NPOS * NOUT];
__device__ float4     g_roi[NBOX];
__device__ ull        g_keyU[NBOX];
__device__ unsigned   g_hist[NBIN];
__device__ unsigned   g_binCnt[NBIN];
__device__ unsigned   g_binPfx[NBIN];
__device__ unsigned   g_gsum[256];
__device__ unsigned   g_cutoff;
__device__ ull        g_binned[NBOX];
__device__ float4     g_sbox[PRE];
__device__ unsigned   g_validBits[NW];
__device__ unsigned   g_mask[(size_t)PRE * MASKW];
__device__ unsigned   g_barCnt;      // zero-initialized
__device__ unsigned   g_barGen;      // zero-initialized

// ------------------ software grid barrier (all NBLK blocks co-resident) ------------------
__device__ __forceinline__ void gridBarrier()
{
    __syncthreads();
    if (threadIdx.x == 0) {
        __threadfence();
        unsigned gen = *(volatile unsigned*)&g_barGen;
        if (atomicAdd(&g_barCnt, 1u) == NBLK - 1) {
            g_barCnt = 0;
            __threadfence();
            *(volatile unsigned*)&g_barGen = gen + 1;
        } else {
            while (*(volatile unsigned*)&g_barGen == gen) { }
        }
        __threadfence();
    }
    __syncthreads();
}

// ------------------ fold ------------------
__global__ __launch_bounds__(192) void fold_kernel(
    const float* __restrict__ W1, const float* __restrict__ Wreg,
    const float* __restrict__ Wcls)
{
    const int t  = threadIdx.x;
    const int g  = t >> 6;
    const int u  = t & 63;
    const int j0 = blockIdx.x * 128;
    const int kh = blockIdx.y;

    __shared__ ull sB[16][128];
    __shared__ ull sH[16 * 48];

    ull a0[15], a1[15];
#pragma unroll
    for (int s = 0; s < 15; s++) { a0[s] = 0ULL; a1[s] = 0ULL; }

    for (int ct = 0; ct < 16; ct++) {
        const int k0 = kh * 512 + ct * 32;
        for (int idx = t; idx < 2048; idx += 192) {
            int cp = idx >> 7, col = idx & 127;
            float lo = W1[(size_t)(k0 + 2 * cp)     * KJ + j0 + col];
            float hi = W1[(size_t)(k0 + 2 * cp + 1) * KJ + j0 + col];
            sB[cp][col] = pack2(lo, hi);
        }
        for (int idx = t; idx < 720; idx += 192) {
            int s = idx >> 4, cp = idx & 15;
            int k = k0 + 2 * cp;
            float lo, hi;
            if (s < 36) { lo = Wreg[s * CMID + k]; hi = Wreg[s * CMID + k + 1]; }
            else {
                int a = s - 36;
                lo = Wcls[(2 * a + 1) * CMID + k];
                hi = Wcls[(2 * a + 1) * CMID + k + 1];
            }
            sH[cp * 48 + (s / 15) * 16 + (s % 15)] = pack2(lo, hi);
        }
        __syncthreads();

#pragma unroll 4
        for (int cp = 0; cp < 16; cp++) {
            ulonglong2 B = *(const ulonglong2*)&sB[cp][2 * u];
            const ull* hp = &sH[cp * 48 + g * 16];
#pragma unroll
            for (int s = 0; s < 15; s += 2) {
                if (s < 14) {
                    ulonglong2 h2 = *(const ulonglong2*)&hp[s];
                    a0[s]   = ffma2(h2.x, B.x, a0[s]);
                    a1[s]   = ffma2(h2.x, B.y, a1[s]);
                    a0[s+1] = ffma2(h2.y, B.x, a0[s+1]);
                    a1[s+1] = ffma2(h2.y, B.y, a1[s+1]);
                } else {
                    ull h = hp[s];
                    a0[s] = ffma2(h, B.x, a0[s]);
                    a1[s] = ffma2(h, B.y, a1[s]);
                }
            }
        }
        __syncthreads();
    }

    float* dst = kh ? g_WfP1 : g_WfP0;
    const int jA = j0 + 2 * u;
#pragma unroll
    for (int s = 0; s < 15; s++) {
        float l0, h0, l1, h1;
        unpack2(a0[s], l0, h0);
        unpack2(a1[s], l1, h1);
        dst[(size_t)jA * NOUT + g * 15 + s]       = l0 + h0;
        dst[(size_t)(jA + 1) * NOUT + g * 15 + s] = l1 + h1;
    }
}

// ------------------ prep: sumw | bias | zero ------------------
__global__ void prep_kernel(const float* __restrict__ Wreg, const float* __restrict__ breg,
                            const float* __restrict__ Wcls, const float* __restrict__ bcls,
                            const float* __restrict__ b1)
{
    const int b = blockIdx.x;
    const int t = threadIdx.x;

    if (b < SUMW_BLOCKS) {
        int idx = b * 256 + t;
        if (idx >= CIN * 9 * NOUT) return;
        int c   = idx / 405;
        int r   = idx - c * 405;
        int ky  = r / 135;
        int r2  = r - ky * 135;
        int kx  = r2 / 45;
        int ch  = r2 - kx * 45;
        size_t j = (size_t)(c * 9 + ky * 3 + kx) * NOUT + ch;
        float v = g_WfP0[j] + g_WfP1[j];
        int og = ch / 3, i = ch - og * 3;
        g_WeffT[(size_t)(c >> 2) * WT_TILE + (kx * 3 + i) * WT_KX
                + ((c & 3) * 3 + ky) * 16 + og] = pack2(v, v);
    } else if (b < SUMW_BLOCKS + BIAS_BLOCKS) {
        __shared__ float sp[8];
        const int ch = b - SUMW_BLOCKS;
        const float* row;
        float hb;
        if (ch < 36) { row = Wreg + ch * CMID; hb = breg[ch]; }
        else         { int a = ch - 36; row = Wcls + (2 * a + 1) * CMID; hb = bcls[2 * a + 1]; }
        float acc = 0.f;
        for (int k = t; k < CMID; k += 256) acc = fmaf(row[k], b1[k], acc);
#pragma unroll
        for (int o = 16; o > 0; o >>= 1) acc += __shfl_down_sync(0xFFFFFFFFu, acc, o);
        if ((t & 31) == 0) sp[t >> 5] = acc;
        __syncthreads();
        if (t == 0) {
            float s = 0.f;
#pragma unroll
            for (int q = 0; q < 8; q++) s += sp[q];
            g_bias[ch] = hb + s;
        }
    } else {
        int i = (b - SUMW_BLOCKS - BIAS_BLOCKS) * 256 + t;
        if (i < NBIN) { g_hist[i] = 0u; g_binCnt[i] = 0u; }
        if (i < NW)   g_validBits[i] = 0u;
        if (i < 256)  g_gsum[i] = 0u;
        uint4* m4 = (uint4*)g_mask;
        for (int q = i; q < PRE * MASKW / 4; q += 65536)
            m4[q] = make_uint4(0u, 0u, 0u, 0u);
    }
}

// ------------------ main folded conv (unchanged from R13 best) ------------------
__global__ __launch_bounds__(160, 4) void main_kernel(const float* __restrict__ feat)
{
    const int t  = threadIdx.x;
    const int cs = blockIdx.x;
    const int yg = blockIdx.y;

    const int og = t % 15;
    const int xg = (t / 15) % 5;
    const int ys = t / 75;
    const bool act = (t < 150);
    const int y  = yg * 2 + ys;
    const int mb = xg * 5;

    __shared__ __align__(16) ull sE[2][E_TILE];
    __shared__ __align__(16) ull sW[2][WT_TILE];

    const unsigned sE0 = (unsigned)__cvta_generic_to_shared(&sE[0][0]);
    const unsigned sE1 = (unsigned)__cvta_generic_to_shared(&sE[1][0]);
    const unsigned sW0 = (unsigned)__cvta_generic_to_shared(&sW[0][0]);
    const unsigned sW1 = (unsigned)__cvta_generic_to_shared(&sW[1][0]);

    ull acc[3][5];
#pragma unroll
    for (int i = 0; i < 3; i++)
#pragma unroll
        for (int m = 0; m < 5; m++) acc[i][m] = 0ULL;

#define STAGE(ct_, eAddr_, wAddr_) do {                                               \
        const int c0_ = cs * 128 + (ct_) * 4;                                         \
        for (int q = t; q < E_TILE; q += 160) {                                       \
            int cr = q / 27, c = q - cr * 27;                                         \
            int cc = cr >> 2, r = cr & 3;                                             \
            int gy = yg * 2 - 1 + r;                                                  \
            bool ok = (c >= 1 && c <= 25 && gy >= 0 && gy < FEAT);                    \
            const float* gp = ok ? &feat[(size_t)(c0_ + cc) * NPOS + gy * FEAT + 2 * (c - 1)] : feat; \
            int sz = ok ? 8 : 0;                                                      \
            asm volatile("cp.async.ca.shared.global [%0], [%1], 8, %2;"               \
                         :: "r"((eAddr_) + q * 8), "l"(gp), "r"(sz));                 \
        }                                                                             \
        const ull* wsrc_ = &g_WeffT[(size_t)(cs * 32 + (ct_)) * WT_TILE];             \
        for (int q = t; q < WT_TILE / 2; q += 160) {                                  \
            asm volatile("cp.async.ca.shared.global [%0], [%1], 16;"                  \
                         :: "r"((wAddr_) + q * 16), "l"(wsrc_ + 2 * q));              \
        }                                                                             \
        asm volatile("cp.async.commit_group;");                                       \
    } while (0)

    STAGE(0, sE0, sW0);

    for (int ct = 0; ct < 32; ct++) {
        const int buf = ct & 1;
        if (ct < 31) {
            if (buf == 0) STAGE(ct + 1, sE1, sW1);
            else          STAGE(ct + 1, sE0, sW0);
            asm volatile("cp.async.wait_group 1;");
        } else {
            asm volatile("cp.async.wait_group 0;");
        }
        __syncthreads();

        if (act) {
            const ull* eB = sE[buf];
            const ull* wB = sW[buf];
            for (int cc = 0; cc < 4; cc++) {
#pragma unroll
                for (int ky = 0; ky < 3; ky++) {
                    const ull* eb = &eB[(cc * 4 + ys + ky) * 27 + mb];
                    const ull* wk = &wB[(cc * 3 + ky) * 16 + og];
                    ull w00 = wk[0];
                    ull w01 = wk[WT_KX];
                    ull w02 = wk[2 * WT_KX];
                    ull w10 = wk[3 * WT_KX];
                    ull w11 = wk[4 * WT_KX];
                    ull w12 = wk[5 * WT_KX];
                    ull w20 = wk[6 * WT_KX];
                    ull w21 = wk[7 * WT_KX];
                    ull w22 = wk[8 * WT_KX];

                    ull Ep = eb[0];
                    ull Ec = eb[1];
                    float epl, eph, ecl, ech;
                    unpack2(Ep, epl, eph);
                    unpack2(Ec, ecl, ech);
                    ull Oc = pack2(eph, ecl);
#pragma unroll
                    for (int m = 0; m < 5; m++) {
                        ull En = eb[m + 2];
                        float enl, enh; unpack2(En, enl, enh);
                        ull On = pack2(ech, enl);
                        acc[0][m] = ffma2(w00, Oc, ffma2(w10, Ec, ffma2(w20, On, acc[0][m])));
                        acc[1][m] = ffma2(w01, Oc, ffma2(w11, Ec, ffma2(w21, On, acc[1][m])));
                        acc[2][m] = ffma2(w02, Oc, ffma2(w12, Ec, ffma2(w22, On, acc[2][m])));
                        Oc = On; Ec = En; ech = enh;
                    }
                }
            }
        }
        __syncthreads();
    }
#undef STAGE

    if (act) {
        float* dst = &g_Psplit[(size_t)cs * (NPOS * NOUT)];
        int pb = y * FEAT + 2 * mb;
#pragma unroll
        for (int i = 0; i < 3; i++) {
            int ch = og * 3 + i;
#pragma unroll
            for (int m = 0; m < 5; m++) {
                float lo, hi; unpack2(acc[i][m], lo, hi);
                dst[(pb + 2 * m)     * NOUT + ch] = lo;
                dst[(pb + 2 * m + 1) * NOUT + ch] = hi;
            }
        }
    }
}

// ------------------ fused post-processing: decode..nms in ONE persistent kernel ------------------
__global__ __launch_bounds__(256) void post_kernel(const float* __restrict__ anchors,
                                                   float* __restrict__ out)
{
    const int t   = threadIdx.x;
    const int bid = blockIdx.x;

    __shared__ float sv[32][46];
    __shared__ float4 jb[32];
    __shared__ unsigned sg[256];
    __shared__ unsigned red[8];
    __shared__ unsigned ws[8];
    __shared__ unsigned sgbase;

    // ---- phase 1: reduce + decode + histograms ----
    for (int g = bid; g < (NPOS + 31) / 32; g += NBLK) {
        const int p0 = g * 32;
        for (int e = t; e < 32 * 45; e += 256) {
            int pL = e / 45, ch = e - pL * 45;
            int p = p0 + pL;
            if (p < NPOS) {
                float s = g_bias[ch];
#pragma unroll
                for (int sp = 0; sp < NSPLIT; sp++)
                    s += g_Psplit[(size_t)sp * (NPOS * NOUT) + p * NOUT + ch];
                sv[pL][ch] = s;
            }
        }
        __syncthreads();
        for (int e = t; e < 288; e += 256) {
            int pL = e / 9, a = e - pL * 9;
            int p = p0 + pL;
            if (p < NPOS) {
                int i = p * 9 + a;
                float v0 = sv[pL][a * 4 + 0];
                float v1 = sv[pL][a * 4 + 1];
                float v2 = sv[pL][a * 4 + 2];
                float v3 = sv[pL][a * 4 + 3];
                float v4 = sv[pL][36 + a];

                float4 an = *(const float4*)&anchors[i * 4];
                float ah = an.z - an.x, aw = an.w - an.y;
                float acy = an.x + 0.5f * ah, acx = an.y + 0.5f * aw;
                float cy = v0 * ah + acy, cx = v1 * aw + acx;
                float h  = expf(v2) * ah, w  = expf(v3) * aw;

                float r0 = fminf(fmaxf(cy - 0.5f * h, 0.f), 800.f);
                float r1 = fminf(fmaxf(cx - 0.5f * w, 0.f), 800.f);
                float r2 = fminf(fmaxf(cy + 0.5f * h, 0.f), 800.f);
                float r3 = fminf(fmaxf(cx + 0.5f * w, 0.f), 800.f);

                bool valid = ((r2 - r0) >= 16.f) && ((r3 - r1) >= 16.f);
                float score = valid ? v4 : -CUDART_INF_F;

                g_roi[i] = make_float4(r0, r1, r2, r3);

                unsigned f   = __float_as_uint(score);
                unsigned asc = f ^ ((f >> 31) ? 0xFFFFFFFFu : 0x80000000u);
                unsigned hi  = ~asc;
                g_keyU[i] = ((ull)hi << 32) | (unsigned)i;
                atomicAdd(&g_hist[hi >> 16], 1u);
                atomicAdd(&g_gsum[hi >> 24], 1u);
            }
        }
        __syncthreads();
    }
    gridBarrier();

    // ---- phase 2: per-bin global prefix + cutoff ----
    for (int g = bid; g < 256; g += NBLK) {
        const int lane = t & 31, wid = t >> 5;
        sg[t] = g_gsum[t];
        __syncthreads();

        unsigned v = (t < g) ? sg[t] : 0u;
#pragma unroll
        for (int o = 16; o > 0; o >>= 1) v += __shfl_down_sync(0xFFFFFFFFu, v, o);
        if (lane == 0) red[wid] = v;
        __syncthreads();
        if (t == 0) {
            unsigned s = 0;
#pragma unroll
            for (int q = 0; q < 8; q++) s += red[q];
            sgbase = s;
        }
        __syncthreads();
        const unsigned gbase = sgbase;

        unsigned h = g_hist[g * 256 + t];
        unsigned x = h;
#pragma unroll
        for (int o = 1; o < 32; o <<= 1) {
            unsigned y2 = __shfl_up_sync(0xFFFFFFFFu, x, o);
            if (lane >= o) x += y2;
        }
        if (lane == 31) ws[wid] = x;
        __syncthreads();
        unsigned woff = 0;
        for (int q = 0; q < wid; q++) woff += ws[q];
        unsigned incl = woff + x;
        unsigned excl = incl - h;
        g_binPfx[g * 256 + t] = gbase + excl;

        if (gbase + excl < (unsigned)PRE && gbase + incl >= (unsigned)PRE)
            g_cutoff = (unsigned)(g * 256 + t);
        __syncthreads();
    }
    gridBarrier();

    // ---- phase 3: bin-sort scatter ----
    for (int i = bid * 256 + t; i < NBOX; i += NBLK * 256) {
        ull k = g_keyU[i];
        unsigned bin = (unsigned)(k >> 48);
        if (bin <= g_cutoff) {
            unsigned pos = g_binPfx[bin] + atomicAdd(&g_binCnt[bin], 1u);
            g_binned[pos] = k;
        }
    }
    gridBarrier();

    // ---- phase 4: exact rank + scatter top-PRE ----
    {
        unsigned cutoff = g_cutoff;
        int M = (int)(g_binPfx[cutoff] + g_binCnt[cutoff]);
        for (int s = bid * 256 + t; s < M; s += NBLK * 256) {
            ull key = g_binned[s];
            unsigned bin = (unsigned)(key >> 48);
            int base = (int)g_binPfx[bin];
            int cnt  = (int)g_binCnt[bin];
            unsigned rank = (unsigned)base;
            for (int m = base; m < base + cnt; m++)
                rank += (g_binned[m] < key);
            if (rank < (unsigned)PRE) {
                g_sbox[rank] = g_roi[(unsigned)key];
                if ((unsigned)(key >> 32) < 0xFF800000u)
                    atomicOr(&g_validBits[rank >> 5], 1u << (rank & 31));
            }
        }
    }
    gridBarrier();

    // ---- phase 5: suppression bitmask ----
    for (int tl = bid; tl < 24 * NW; tl += NBLK) {
        int ib = tl / NW, jt = tl - ib * NW;
        if (jt * 32 + 31 <= ib * 256) continue;    // uniform per block
        int j0 = jt * 32;
        __syncthreads();
        if (t < 32) {
            int jj = j0 + t;
            jb[t] = (jj < PRE) ? g_sbox[jj] : make_float4(1e9f, 1e9f, 1e9f, 1e9f);
        }
        __syncthreads();
        int i = ib * 256 + t;
        if (i < PRE) {
            float4 bi = g_sbox[i];
            float areai = (bi.w - bi.y + 1.f) * (bi.z - bi.x + 1.f);
            unsigned word = 0u;
#pragma unroll 8
            for (int q = 0; q < 32; q++) {
                int j = j0 + q;
                if (j > i) {
                    float4 bj = jb[q];
                    float yy1 = fmaxf(bi.x, bj.x), xx1 = fmaxf(bi.y, bj.y);
                    float yy2 = fminf(bi.z, bj.z), xx2 = fminf(bi.w, bj.w);
                    float inter = fmaxf(0.f, xx2 - xx1 + 1.f) * fmaxf(0.f, yy2 - yy1 + 1.f);
                    float areaj = (bj.w - bj.y + 1.f) * (bj.z - bj.x + 1.f);
                    if (inter > 0.7f * (areai + areaj - inter)) word |= (1u << q);
                }
            }
            g_mask[(size_t)i * MASKW + jt] = word;
        }
    }
    gridBarrier();

    // ---- phase 6: serial greedy NMS (block 0, warp 0, 2-pick speculation) ----
    if (bid != 0 || t >= 32) return;
    {
        const int lane = t;
        unsigned val[6], rem[6];
#pragma unroll
        for (int q = 0; q < 6; q++) {
            int w = 6 * lane + q;
            val[q] = (w < NW) ? g_validBits[w] : 0u;
            rem[q] = 0u;
        }
        for (int k = lane; k < POST * 4; k += 32) out[k] = 0.f;
        __syncwarp();

        int kept = 0;
        while (kept < POST) {
            int cand = 0x7FFFFFFF;
#pragma unroll
            for (int q = 0; q < 6; q++) {
                unsigned a = val[q] & ~rem[q];
                if (a && cand == 0x7FFFFFFF)
                    cand = (6 * lane + q) * 32 + __ffs(a) - 1;
            }
            int i = __reduce_min_sync(0xFFFFFFFFu, cand);
            if (i == 0x7FFFFFFF) break;
            {
                int ql = (i >> 5) - 6 * lane;
                if (ql >= 0 && ql < 6) val[ql] &= ~(1u << (i & 31));
            }
            cand = 0x7FFFFFFF;
#pragma unroll
            for (int q = 0; q < 6; q++) {
                unsigned a = val[q] & ~rem[q];
                if (a && cand == 0x7FFFFFFF)
                    cand = (6 * lane + q) * 32 + __ffs(a) - 1;
            }
            int j = __reduce_min_sync(0xFFFFFFFFu, cand);

            const uint2* rA = (const uint2*)(g_mask + (size_t)i * MASKW);
            uint2 a0 = __ldg(&rA[3 * lane]);
            uint2 a1 = __ldg(&rA[3 * lane + 1]);
            uint2 a2 = __ldg(&rA[3 * lane + 2]);
            uint2 b0 = make_uint2(0u, 0u), b1 = make_uint2(0u, 0u), b2 = make_uint2(0u, 0u);
            if (j != 0x7FFFFFFF) {
                const uint2* rB = (const uint2*)(g_mask + (size_t)j * MASKW);
                b0 = __ldg(&rB[3 * lane]);
                b1 = __ldg(&rB[3 * lane + 1]);
                b2 = __ldg(&rB[3 * lane + 2]);
            }

            if (lane == 0) *(float4*)&out[kept * 4] = g_sbox[i];
            kept++;

            bool accept = false;
            if (j != 0x7FFFFFFF && kept < POST) {
                int wj = j >> 5;
                int owner = wj / 6, sub = wj - owner * 6;
                unsigned myw = (sub == 0) ? a0.x : (sub == 1) ? a0.y :
                               (sub == 2) ? a1.x : (sub == 3) ? a1.y :
                               (sub == 4) ? a2.x : a2.y;
                unsigned wv = __shfl_sync(0xFFFFFFFFu, myw, owner);
                accept = ((wv >> (j & 31)) & 1u) == 0u;
            }

            rem[0] |= a0.x; rem[1] |= a0.y;
            rem[2] |= a1.x; rem[3] |= a1.y;
            rem[4] |= a2.x; rem[5] |= a2.y;
            if (accept) {
                rem[0] |= b0.x; rem[1] |= b0.y;
                rem[2] |= b1.x; rem[3] |= b1.y;
                rem[4] |= b2.x; rem[5] |= b2.y;
                int ql = (j >> 5) - 6 * lane;
                if (ql >= 0 && ql < 6) val[ql] &= ~(1u << (j & 31));
                if (lane == 0) *(float4*)&out[kept * 4] = g_sbox[j];
                kept++;
            }
        }
    }
}

// ------------------ launch ------------------
extern "C" void kernel_launch(void* const* d_in, const int* in_sizes, int n_in,
                              void* d_out, int out_size)
{
    const float* feat    = (const float*)d_in[0];
    const float* anchors = (const float*)d_in[1];
    const float* W1      = (const float*)d_in[2];
    const float* b1      = (const float*)d_in[3];
    const float* Wreg    = (const float*)d_in[4];
    const float* breg    = (const float*)d_in[5];
    const float* Wcls    = (const float*)d_in[6];
    const float* bcls    = (const float*)d_in[7];
    float* out = (float*)d_out;

    fold_kernel<<<dim3(144, 2), 192>>>(W1, Wreg, Wcls);
    prep_kernel<<<PREP_BLOCKS, 256>>>(Wreg, breg, Wcls, bcls, b1);
    main_kernel<<<dim3(16, 25), 160>>>(feat);
    post_kernel<<<NBLK, 256>>>(anchors, out);
}

// round 15
// speedup vs baseline: 1.0620x; 1.0620x over previous
#include <cuda_runtime.h>
#include <cuda_bf16.h>
#include <math_constants.h>

#define FEAT 50
#define NPOS 2500
#define NBOX 22500
#define CIN 2048
#define CMID 1024
#define KJ (CIN*9)
#define NOUT 45
#define NSPLIT 16
#define PRE 6000
#define POST 300
#define NW 188
#define MASKW 192
#define NBIN 65536

#define WT_TILE 1728           // ull per 4-channel group: 9 planes x 12 (cc,ky) x 16 og
#define WT_KX   192            // plane stride = 12*16
#define E_TILE  432            // 4 ch x 4 rows x 27 cols

#define SUMW_BLOCKS 3240       // (CIN*9*NOUT)/256
#define BIAS_BLOCKS 45
#define ZERO_BLOCKS 256
#define PREP_BLOCKS (SUMW_BLOCKS + BIAS_BLOCKS + ZERO_BLOCKS)

#define NBLK 592               // persistent post-kernel blocks: 4 per SM, all co-resident

typedef unsigned long long ull;

__device__ __forceinline__ ull pack2(float lo, float hi) {
    ull d; asm("mov.b64 %0, {%1, %2};" : "=l"(d) : "f"(lo), "f"(hi)); return d;
}
__device__ __forceinline__ void unpack2(ull p, float& lo, float& hi) {
    asm("mov.b64 {%0, %1}, %2;" : "=f"(lo), "=f"(hi) : "l"(p));
}
__device__ __forceinline__ ull ffma2(ull a, ull b, ull c) {
    ull d; asm("fma.rn.f32x2 %0, %1, %2, %3;" : "=l"(d) : "l"(a), "l"(b), "l"(c)); return d;
}

// ------------------ scratch ------------------
__device__ float      g_WfP0[(size_t)KJ * NOUT];
__device__ float      g_WfP1[(size_t)KJ * NOUT];
__device__ ull        g_WeffT[(size_t)(CIN / 4) * WT_TILE];
__device__ float      g_bias[NOUT];
__device__ float      g_Psplit[NSPLIT * NPOS * NOUT];
__device__ float4     g_roi[NBOX];
__device__ ull        g_keyU[NBOX];
__device__ unsigned   g_hist[NBIN];
__device__ unsigned   g_binCnt[NBIN];
__device__ unsigned   g_binPfx[NBIN];
__device__ unsigned   g_gsum[256];
__device__ unsigned   g_cutoff;
__device__ ull        g_binned[NBOX];
__device__ float4     g_sbox[PRE];
__device__ unsigned   g_validBits[NW];
__device__ unsigned   g_mask[(size_t)PRE * MASKW];
__device__ unsigned   g_barCnt;      // zero-initialized
__device__ unsigned   g_barGen;      // zero-initialized

// ------------------ software grid barrier (all NBLK blocks co-resident) ------------------
__device__ __forceinline__ void gridBarrier()
{
    __syncthreads();
    if (threadIdx.x == 0) {
        __threadfence();
        unsigned gen = *(volatile unsigned*)&g_barGen;
        if (atomicAdd(&g_barCnt, 1u) == NBLK - 1) {
            g_barCnt = 0;
            __threadfence();
            *(volatile unsigned*)&g_barGen = gen + 1;
        } else {
            while (*(volatile unsigned*)&g_barGen == gen) { }
        }
        __threadfence();
    }
    __syncthreads();
}

// ------------------ fold ------------------
__global__ __launch_bounds__(192) void fold_kernel(
    const float* __restrict__ W1, const float* __restrict__ Wreg,
    const float* __restrict__ Wcls)
{
    const int t  = threadIdx.x;
    const int g  = t >> 6;
    const int u  = t & 63;
    const int j0 = blockIdx.x * 128;
    const int kh = blockIdx.y;

    __shared__ ull sB[16][128];
    __shared__ ull sH[16 * 48];

    ull a0[15], a1[15];
#pragma unroll
    for (int s = 0; s < 15; s++) { a0[s] = 0ULL; a1[s] = 0ULL; }

    for (int ct = 0; ct < 16; ct++) {
        const int k0 = kh * 512 + ct * 32;
        for (int idx = t; idx < 2048; idx += 192) {
            int cp = idx >> 7, col = idx & 127;
            float lo = W1[(size_t)(k0 + 2 * cp)     * KJ + j0 + col];
            float hi = W1[(size_t)(k0 + 2 * cp + 1) * KJ + j0 + col];
            sB[cp][col] = pack2(lo, hi);
        }
        for (int idx = t; idx < 720; idx += 192) {
            int s = idx >> 4, cp = idx & 15;
            int k = k0 + 2 * cp;
            float lo, hi;
            if (s < 36) { lo = Wreg[s * CMID + k]; hi = Wreg[s * CMID + k + 1]; }
            else {
                int a = s - 36;
                lo = Wcls[(2 * a + 1) * CMID + k];
                hi = Wcls[(2 * a + 1) * CMID + k + 1];
            }
            sH[cp * 48 + (s / 15) * 16 + (s % 15)] = pack2(lo, hi);
        }
        __syncthreads();

#pragma unroll 4
        for (int cp = 0; cp < 16; cp++) {
            ulonglong2 B = *(const ulonglong2*)&sB[cp][2 * u];
            const ull* hp = &sH[cp * 48 + g * 16];
#pragma unroll
            for (int s = 0; s < 15; s += 2) {
                if (s < 14) {
                    ulonglong2 h2 = *(const ulonglong2*)&hp[s];
                    a0[s]   = ffma2(h2.x, B.x, a0[s]);
                    a1[s]   = ffma2(h2.x, B.y, a1[s]);
                    a0[s+1] = ffma2(h2.y, B.x, a0[s+1]);
                    a1[s+1] = ffma2(h2.y, B.y, a1[s+1]);
                } else {
                    ull h = hp[s];
                    a0[s] = ffma2(h, B.x, a0[s]);
                    a1[s] = ffma2(h, B.y, a1[s]);
                }
            }
        }
        __syncthreads();
    }

    float* dst = kh ? g_WfP1 : g_WfP0;
    const int jA = j0 + 2 * u;
#pragma unroll
    for (int s = 0; s < 15; s++) {
        float l0, h0, l1, h1;
        unpack2(a0[s], l0, h0);
        unpack2(a1[s], l1, h1);
        dst[(size_t)jA * NOUT + g * 15 + s]       = l0 + h0;
        dst[(size_t)(jA + 1) * NOUT + g * 15 + s] = l1 + h1;
    }
}

// ------------------ prep: sumw | bias | zero ------------------
__global__ void prep_kernel(const float* __restrict__ Wreg, const float* __restrict__ breg,
                            const float* __restrict__ Wcls, const float* __restrict__ bcls,
                            const float* __restrict__ b1)
{
    const int b = blockIdx.x;
    const int t = threadIdx.x;

    if (b < SUMW_BLOCKS) {
        int idx = b * 256 + t;
        if (idx >= CIN * 9 * NOUT) return;
        int c   = idx / 405;
        int r   = idx - c * 405;
        int ky  = r / 135;
        int r2  = r - ky * 135;
        int kx  = r2 / 45;
        int ch  = r2 - kx * 45;
        size_t j = (size_t)(c * 9 + ky * 3 + kx) * NOUT + ch;
        float v = g_WfP0[j] + g_WfP1[j];
        int og = ch / 3, i = ch - og * 3;
        g_WeffT[(size_t)(c >> 2) * WT_TILE + (kx * 3 + i) * WT_KX
                + ((c & 3) * 3 + ky) * 16 + og] = pack2(v, v);
    } else if (b < SUMW_BLOCKS + BIAS_BLOCKS) {
        __shared__ float sp[8];
        const int ch = b - SUMW_BLOCKS;
        const float* row;
        float hb;
        if (ch < 36) { row = Wreg + ch * CMID; hb = breg[ch]; }
        else         { int a = ch - 36; row = Wcls + (2 * a + 1) * CMID; hb = bcls[2 * a + 1]; }
        float acc = 0.f;
        for (int k = t; k < CMID; k += 256) acc = fmaf(row[k], b1[k], acc);
#pragma unroll
        for (int o = 16; o > 0; o >>= 1) acc += __shfl_down_sync(0xFFFFFFFFu, acc, o);
        if ((t & 31) == 0) sp[t >> 5] = acc;
        __syncthreads();
        if (t == 0) {
            float s = 0.f;
#pragma unroll
            for (int q = 0; q < 8; q++) s += sp[q];
            g_bias[ch] = hb + s;
        }
    } else {
        int i = (b - SUMW_BLOCKS - BIAS_BLOCKS) * 256 + t;
        if (i < NBIN) { g_hist[i] = 0u; g_binCnt[i] = 0u; }
        if (i < NW)   g_validBits[i] = 0u;
        if (i < 256)  g_gsum[i] = 0u;
        uint4* m4 = (uint4*)g_mask;
        for (int q = i; q < PRE * MASKW / 4; q += 65536)
            m4[q] = make_uint4(0u, 0u, 0u, 0u);
    }
}

// ------------------ main folded conv (unchanged from R13 best) ------------------
__global__ __launch_bounds__(160, 4) void main_kernel(const float* __restrict__ feat)
{
    const int t  = threadIdx.x;
    const int cs = blockIdx.x;
    const int yg = blockIdx.y;

    const int og = t % 15;
    const int xg = (t / 15) % 5;
    const int ys = t / 75;
    const bool act = (t < 150);
    const int y  = yg * 2 + ys;
    const int mb = xg * 5;

    __shared__ __align__(16) ull sE[2][E_TILE];
    __shared__ __align__(16) ull sW[2][WT_TILE];

    const unsigned sE0 = (unsigned)__cvta_generic_to_shared(&sE[0][0]);
    const unsigned sE1 = (unsigned)__cvta_generic_to_shared(&sE[1][0]);
    const unsigned sW0 = (unsigned)__cvta_generic_to_shared(&sW[0][0]);
    const unsigned sW1 = (unsigned)__cvta_generic_to_shared(&sW[1][0]);

    ull acc[3][5];
#pragma unroll
    for (int i = 0; i < 3; i++)
#pragma unroll
        for (int m = 0; m < 5; m++) acc[i][m] = 0ULL;

#define STAGE(ct_, eAddr_, wAddr_) do {                                               \
        const int c0_ = cs * 128 + (ct_) * 4;                                         \
        for (int q = t; q < E_TILE; q += 160) {                                       \
            int cr = q / 27, c = q - cr * 27;                                         \
            int cc = cr >> 2, r = cr & 3;                                             \
            int gy = yg * 2 - 1 + r;                                                  \
            bool ok = (c >= 1 && c <= 25 && gy >= 0 && gy < FEAT);                    \
            const float* gp = ok ? &feat[(size_t)(c0_ + cc) * NPOS + gy * FEAT + 2 * (c - 1)] : feat; \
            int sz = ok ? 8 : 0;                                                      \
            asm volatile("cp.async.ca.shared.global [%0], [%1], 8, %2;"               \
                         :: "r"((eAddr_) + q * 8), "l"(gp), "r"(sz));                 \
        }                                                                             \
        const ull* wsrc_ = &g_WeffT[(size_t)(cs * 32 + (ct_)) * WT_TILE];             \
        for (int q = t; q < WT_TILE / 2; q += 160) {                                  \
            asm volatile("cp.async.ca.shared.global [%0], [%1], 16;"                  \
                         :: "r"((wAddr_) + q * 16), "l"(wsrc_ + 2 * q));              \
        }                                                                             \
        asm volatile("cp.async.commit_group;");                                       \
    } while (0)

    STAGE(0, sE0, sW0);

    for (int ct = 0; ct < 32; ct++) {
        const int buf = ct & 1;
        if (ct < 31) {
            if (buf == 0) STAGE(ct + 1, sE1, sW1);
            else          STAGE(ct + 1, sE0, sW0);
            asm volatile("cp.async.wait_group 1;");
        } else {
            asm volatile("cp.async.wait_group 0;");
        }
        __syncthreads();

        if (act) {
            const ull* eB = sE[buf];
            const ull* wB = sW[buf];
            for (int cc = 0; cc < 4; cc++) {
#pragma unroll
                for (int ky = 0; ky < 3; ky++) {
                    const ull* eb = &eB[(cc * 4 + ys + ky) * 27 + mb];
                    const ull* wk = &wB[(cc * 3 + ky) * 16 + og];
                    ull w00 = wk[0];
                    ull w01 = wk[WT_KX];
                    ull w02 = wk[2 * WT_KX];
                    ull w10 = wk[3 * WT_KX];
                    ull w11 = wk[4 * WT_KX];
                    ull w12 = wk[5 * WT_KX];
                    ull w20 = wk[6 * WT_KX];
                    ull w21 = wk[7 * WT_KX];
                    ull w22 = wk[8 * WT_KX];

                    ull Ep = eb[0];
                    ull Ec = eb[1];
                    float epl, eph, ecl, ech;
                    unpack2(Ep, epl, eph);
                    unpack2(Ec, ecl, ech);
                    ull Oc = pack2(eph, ecl);
#pragma unroll
                    for (int m = 0; m < 5; m++) {
                        ull En = eb[m + 2];
                        float enl, enh; unpack2(En, enl, enh);
                        ull On = pack2(ech, enl);
                        acc[0][m] = ffma2(w00, Oc, ffma2(w10, Ec, ffma2(w20, On, acc[0][m])));
                        acc[1][m] = ffma2(w01, Oc, ffma2(w11, Ec, ffma2(w21, On, acc[1][m])));
                        acc[2][m] = ffma2(w02, Oc, ffma2(w12, Ec, ffma2(w22, On, acc[2][m])));
                        Oc = On; Ec = En; ech = enh;
                    }
                }
            }
        }
        __syncthreads();
    }
#undef STAGE

    if (act) {
        float* dst = &g_Psplit[(size_t)cs * (NPOS * NOUT)];
        int pb = y * FEAT + 2 * mb;
#pragma unroll
        for (int i = 0; i < 3; i++) {
            int ch = og * 3 + i;
#pragma unroll
            for (int m = 0; m < 5; m++) {
                float lo, hi; unpack2(acc[i][m], lo, hi);
                dst[(pb + 2 * m)     * NOUT + ch] = lo;
                dst[(pb + 2 * m + 1) * NOUT + ch] = hi;
            }
        }
    }
}

// ------------------ fused post-processing: ONE persistent kernel, 4 blocks/SM ------------------
__global__ __launch_bounds__(256, 4) void post_kernel(const float* __restrict__ anchors,
                                                      float* __restrict__ out)
{
    const int t   = threadIdx.x;
    const int bid = blockIdx.x;

    __shared__ float sv[32][46];
    __shared__ float4 jb[32];
    __shared__ unsigned sg[256];
    __shared__ unsigned red[8];
    __shared__ unsigned ws[8];
    __shared__ unsigned sgbase;

    // ---- phase 1: reduce + decode + histograms ----
    for (int g = bid; g < (NPOS + 31) / 32; g += NBLK) {
        const int p0 = g * 32;
        for (int e = t; e < 32 * 45; e += 256) {
            int pL = e / 45, ch = e - pL * 45;
            int p = p0 + pL;
            if (p < NPOS) {
                float s = g_bias[ch];
#pragma unroll
                for (int sp = 0; sp < NSPLIT; sp++)
                    s += g_Psplit[(size_t)sp * (NPOS * NOUT) + p * NOUT + ch];
                sv[pL][ch] = s;
            }
        }
        __syncthreads();
        for (int e = t; e < 288; e += 256) {
            int pL = e / 9, a = e - pL * 9;
            int p = p0 + pL;
            if (p < NPOS) {
                int i = p * 9 + a;
                float v0 = sv[pL][a * 4 + 0];
                float v1 = sv[pL][a * 4 + 1];
                float v2 = sv[pL][a * 4 + 2];
                float v3 = sv[pL][a * 4 + 3];
                float v4 = sv[pL][36 + a];

                float4 an = *(const float4*)&anchors[i * 4];
                float ah = an.z - an.x, aw = an.w - an.y;
                float acy = an.x + 0.5f * ah, acx = an.y + 0.5f * aw;
                float cy = v0 * ah + acy, cx = v1 * aw + acx;
                float h  = expf(v2) * ah, w  = expf(v3) * aw;

                float r0 = fminf(fmaxf(cy - 0.5f * h, 0.f), 800.f);
                float r1 = fminf(fmaxf(cx - 0.5f * w, 0.f), 800.f);
                float r2 = fminf(fmaxf(cy + 0.5f * h, 0.f), 800.f);
                float r3 = fminf(fmaxf(cx + 0.5f * w, 0.f), 800.f);

                bool valid = ((r2 - r0) >= 16.f) && ((r3 - r1) >= 16.f);
                float score = valid ? v4 : -CUDART_INF_F;

                g_roi[i] = make_float4(r0, r1, r2, r3);

                unsigned f   = __float_as_uint(score);
                unsigned asc = f ^ ((f >> 31) ? 0xFFFFFFFFu : 0x80000000u);
                unsigned hi  = ~asc;
                g_keyU[i] = ((ull)hi << 32) | (unsigned)i;
                atomicAdd(&g_hist[hi >> 16], 1u);
                atomicAdd(&g_gsum[hi >> 24], 1u);
            }
        }
        __syncthreads();
    }
    gridBarrier();

    // ---- phase 2: per-bin global prefix + cutoff ----
    for (int g = bid; g < 256; g += NBLK) {
        const int lane = t & 31, wid = t >> 5;
        sg[t] = g_gsum[t];
        __syncthreads();

        unsigned v = (t < g) ? sg[t] : 0u;
#pragma unroll
        for (int o = 16; o > 0; o >>= 1) v += __shfl_down_sync(0xFFFFFFFFu, v, o);
        if (lane == 0) red[wid] = v;
        __syncthreads();
        if (t == 0) {
            unsigned s = 0;
#pragma unroll
            for (int q = 0; q < 8; q++) s += red[q];
            sgbase = s;
        }
        __syncthreads();
        const unsigned gbase = sgbase;

        unsigned h = g_hist[g * 256 + t];
        unsigned x = h;
#pragma unroll
        for (int o = 1; o < 32; o <<= 1) {
            unsigned y2 = __shfl_up_sync(0xFFFFFFFFu, x, o);
            if (lane >= o) x += y2;
        }
        if (lane == 31) ws[wid] = x;
        __syncthreads();
        unsigned woff = 0;
        for (int q = 0; q < wid; q++) woff += ws[q];
        unsigned incl = woff + x;
        unsigned excl = incl - h;
        g_binPfx[g * 256 + t] = gbase + excl;

        if (gbase + excl < (unsigned)PRE && gbase + incl >= (unsigned)PRE)
            g_cutoff = (unsigned)(g * 256 + t);
        __syncthreads();
    }
    gridBarrier();

    // ---- phase 3: bin-sort scatter ----
    for (int i = bid * 256 + t; i < NBOX; i += NBLK * 256) {
        ull k = g_keyU[i];
        unsigned bin = (unsigned)(k >> 48);
        if (bin <= g_cutoff) {
            unsigned pos = g_binPfx[bin] + atomicAdd(&g_binCnt[bin], 1u);
            g_binned[pos] = k;
        }
    }
    gridBarrier();

    // ---- phase 4: exact rank + scatter top-PRE ----
    {
        unsigned cutoff = g_cutoff;
        int M = (int)(g_binPfx[cutoff] + g_binCnt[cutoff]);
        for (int s = bid * 256 + t; s < M; s += NBLK * 256) {
            ull key = g_binned[s];
            unsigned bin = (unsigned)(key >> 48);
            int base = (int)g_binPfx[bin];
            int cnt  = (int)g_binCnt[bin];
            unsigned rank = (unsigned)base;
            for (int m = base; m < base + cnt; m++)
                rank += (g_binned[m] < key);
            if (rank < (unsigned)PRE) {
                g_sbox[rank] = g_roi[(unsigned)key];
                if ((unsigned)(key >> 32) < 0xFF800000u)
                    atomicOr(&g_validBits[rank >> 5], 1u << (rank & 31));
            }
        }
    }
    gridBarrier();

    // ---- phase 5: suppression bitmask ----
    for (int tl = bid; tl < 24 * NW; tl += NBLK) {
        int ib = tl / NW, jt = tl - ib * NW;
        if (jt * 32 + 31 <= ib * 256) continue;    // uniform per block
        int j0 = jt * 32;
        __syncthreads();
        if (t < 32) {
            int jj = j0 + t;
            jb[t] = (jj < PRE) ? g_sbox[jj] : make_float4(1e9f, 1e9f, 1e9f, 1e9f);
        }
        __syncthreads();
        int i = ib * 256 + t;
        if (i < PRE) {
            float4 bi = g_sbox[i];
            float areai = (bi.w - bi.y + 1.f) * (bi.z - bi.x + 1.f);
            unsigned word = 0u;
#pragma unroll 8
            for (int q = 0; q < 32; q++) {
                int j = j0 + q;
                if (j > i) {
                    float4 bj = jb[q];
                    float yy1 = fmaxf(bi.x, bj.x), xx1 = fmaxf(bi.y, bj.y);
                    float yy2 = fminf(bi.z, bj.z), xx2 = fminf(bi.w, bj.w);
                    float inter = fmaxf(0.f, xx2 - xx1 + 1.f) * fmaxf(0.f, yy2 - yy1 + 1.f);
                    float areaj = (bj.w - bj.y + 1.f) * (bj.z - bj.x + 1.f);
                    if (inter > 0.7f * (areai + areaj - inter)) word |= (1u << q);
                }
            }
            g_mask[(size_t)i * MASKW + jt] = word;
        }
    }
    gridBarrier();

    // ---- phase 6: serial greedy NMS (block 0, warp 0, 2-pick speculation) ----
    if (bid != 0 || t >= 32) return;
    {
        const int lane = t;
        unsigned val[6], rem[6];
#pragma unroll
        for (int q = 0; q < 6; q++) {
            int w = 6 * lane + q;
            val[q] = (w < NW) ? g_validBits[w] : 0u;
            rem[q] = 0u;
        }
        for (int k = lane; k < POST * 4; k += 32) out[k] = 0.f;
        __syncwarp();

        int kept = 0;
        while (kept < POST) {
            int cand = 0x7FFFFFFF;
#pragma unroll
            for (int q = 0; q < 6; q++) {
                unsigned a = val[q] & ~rem[q];
                if (a && cand == 0x7FFFFFFF)
                    cand = (6 * lane + q) * 32 + __ffs(a) - 1;
            }
            int i = __reduce_min_sync(0xFFFFFFFFu, cand);
            if (i == 0x7FFFFFFF) break;
            {
                int ql = (i >> 5) - 6 * lane;
                if (ql >= 0 && ql < 6) val[ql] &= ~(1u << (i & 31));
            }
            cand = 0x7FFFFFFF;
#pragma unroll
            for (int q = 0; q < 6; q++) {
                unsigned a = val[q] & ~rem[q];
                if (a && cand == 0x7FFFFFFF)
                    cand = (6 * lane + q) * 32 + __ffs(a) - 1;
            }
            int j = __reduce_min_sync(0xFFFFFFFFu, cand);

            const uint2* rA = (const uint2*)(g_mask + (size_t)i * MASKW);
            uint2 a0 = __ldg(&rA[3 * lane]);
            uint2 a1 = __ldg(&rA[3 * lane + 1]);
            uint2 a2 = __ldg(&rA[3 * lane + 2]);
            uint2 b0 = make_uint2(0u, 0u), b1 = make_uint2(0u, 0u), b2 = make_uint2(0u, 0u);
            if (j != 0x7FFFFFFF) {
                const uint2* rB = (const uint2*)(g_mask + (size_t)j * MASKW);
                b0 = __ldg(&rB[3 * lane]);
                b1 = __ldg(&rB[3 * lane + 1]);
                b2 = __ldg(&rB[3 * lane + 2]);
            }

            if (lane == 0) *(float4*)&out[kept * 4] = g_sbox[i];
            kept++;

            bool accept = false;
            if (j != 0x7FFFFFFF && kept < POST) {
                int wj = j >> 5;
                int owner = wj / 6, sub = wj - owner * 6;
                unsigned myw = (sub == 0) ? a0.x : (sub == 1) ? a0.y :
                               (sub == 2) ? a1.x : (sub == 3) ? a1.y :
                               (sub == 4) ? a2.x : a2.y;
                unsigned wv = __shfl_sync(0xFFFFFFFFu, myw, owner);
                accept = ((wv >> (j & 31)) & 1u) == 0u;
            }

            rem[0] |= a0.x; rem[1] |= a0.y;
            rem[2] |= a1.x; rem[3] |= a1.y;
            rem[4] |= a2.x; rem[5] |= a2.y;
            if (accept) {
                rem[0] |= b0.x; rem[1] |= b0.y;
                rem[2] |= b1.x; rem[3] |= b1.y;
                rem[4] |= b2.x; rem[5] |= b2.y;
                int ql = (j >> 5) - 6 * lane;
                if (ql >= 0 && ql < 6) val[ql] &= ~(1u << (j & 31));
                if (lane == 0) *(float4*)&out[kept * 4] = g_sbox[j];
                kept++;
            }
        }
    }
}

// ------------------ launch ------------------
extern "C" void kernel_launch(void* const* d_in, const int* in_sizes, int n_in,
                              void* d_out, int out_size)
{
    const float* feat    = (const float*)d_in[0];
    const float* anchors = (const float*)d_in[1];
    const float* W1      = (const float*)d_in[2];
    const float* b1      = (const float*)d_in[3];
    const float* Wreg    = (const float*)d_in[4];
    const float* breg    = (const float*)d_in[5];
    const float* Wcls    = (const float*)d_in[6];
    const float* bcls    = (const float*)d_in[7];
    float* out = (float*)d_out;

    fold_kernel<<<dim3(144, 2), 192>>>(W1, Wreg, Wcls);
    prep_kernel<<<PREP_BLOCKS, 256>>>(Wreg, breg, Wcls, bcls, b1);
    main_kernel<<<dim3(16, 25), 160>>>(feat);
    post_kernel<<<NBLK, 256>>>(anchors, out);
}